// round 14
// baseline (speedup 1.0000x reference)
#include <cuda_runtime.h>
#include <cuda_fp16.h>
#include <math.h>
#include <stdint.h>

// ---------------- problem constants ----------------
#define BATCH 4
#define INC   32
#define OUTC  64
#define HW    56
#define PH    58
#define MTOT  (BATCH*HW*HW)              // 12544
#define NPIX  (BATCH*PH*PH)              // 13456 padded pixels
#define KSPL  2304                       // 9 taps * 256
#define KBAS  288                        // 9 taps * 32
#define NCH_S 72                         // spline chunks of k=32
#define NCH   81                         // + 9 base chunks
#define CPB   27                         // chunks per block (81/3)
#define NMT   (MTOT/64)                  // 196 m-tiles

// ---------------- scratch ----------------
__device__ __half g_fh[NPIX*256];        // basis features fp16 [pix][c*8+f]
__device__ __half g_xph[NPIX*32];        // raw x fp16          [pix][c]
__device__ __half g_wsh[OUTC*KSPL];      // spline W fp16 [o][k]
__device__ __half g_wbh[OUTC*KBAS];      // base W fp16   [o][k]
__device__ float  g_S[3*MTOT*OUTC];      // spline split-K partials [z][m][o]
__device__ float  g_Bc[MTOT*OUTC];       // base conv result        [m][o]
__device__ int    g_cnt[NMT];            // per-m-tile completion counters

// ---------------- helpers ----------------
__device__ __forceinline__ uint32_t smem_u32(const void* p) {
    uint32_t a;
    asm("{ .reg .u64 t; cvta.to.shared.u64 t, %1; cvt.u32.u64 %0, t; }" : "=r"(a) : "l"(p));
    return a;
}
#define CPA16(sm, gp) asm volatile("cp.async.cg.shared.global [%0], [%1], 16;" :: "r"(sm), "l"(gp))
#define CP_COMMIT()   asm volatile("cp.async.commit_group;" ::: "memory")
#define CP_WAIT1()    asm volatile("cp.async.wait_group 1;" ::: "memory")
#define CP_WAIT0()    asm volatile("cp.async.wait_group 0;" ::: "memory")

#define LDSM4(r, addr) \
    asm volatile("ldmatrix.sync.aligned.m8n8.x4.shared.b16 {%0,%1,%2,%3}, [%4];" \
        : "=r"((r)[0]), "=r"((r)[1]), "=r"((r)[2]), "=r"((r)[3]) : "r"(addr))

__device__ __forceinline__ void mma16816(float* d, const uint32_t* a, uint32_t b0, uint32_t b1) {
    asm volatile(
        "mma.sync.aligned.m16n8k16.row.col.f32.f16.f16.f32 "
        "{%0,%1,%2,%3}, {%4,%5,%6,%7}, {%8,%9}, {%0,%1,%2,%3};"
        : "+f"(d[0]), "+f"(d[1]), "+f"(d[2]), "+f"(d[3])
        : "r"(a[0]), "r"(a[1]), "r"(a[2]), "r"(a[3]), "r"(b0), "r"(b1));
}

// ---------------- knots / bspline ----------------
__device__ __forceinline__ float knot(int i) { return (float)(i - 3) * 0.4f - 1.0f; }

__device__ __forceinline__ void bspline8(float xv, float* out8) {
    float bb[11];
#pragma unroll
    for (int i = 0; i < 11; i++)
        bb[i] = (xv >= knot(i) && xv < knot(i + 1)) ? 1.0f : 0.0f;
    const float RK1 = 2.5f, RK2 = 1.25f, RK3 = 1.0f / 1.2f;
#pragma unroll
    for (int i = 0; i < 10; i++)
        bb[i] = (xv - knot(i)) * RK1 * bb[i] + (knot(i + 2) - xv) * RK1 * bb[i + 1];
#pragma unroll
    for (int i = 0; i < 9; i++)
        bb[i] = (xv - knot(i)) * RK2 * bb[i] + (knot(i + 3) - xv) * RK2 * bb[i + 1];
#pragma unroll
    for (int i = 0; i < 8; i++)
        bb[i] = (xv - knot(i)) * RK3 * bb[i] + (knot(i + 4) - xv) * RK3 * bb[i + 1];
#pragma unroll
    for (int i = 0; i < 8; i++) out8[i] = bb[i];
}

// ---------------- kernel 1: prep (pack weights + basis fill + zero counters) ----------------
__global__ void prep_kernel(const float* __restrict__ x,
                            const float* __restrict__ sw,
                            const float* __restrict__ bw)
{
    int t = blockIdx.x * blockDim.x + threadIdx.x;
    const int NSPL = OUTC * INC * 9;     // 18432 (one thread per 8 f-values)
    const int NBAS = OUTC * KBAS;        // 18432

    if (t < NMT) g_cnt[t] = 0;

    if (t < NSPL) {
        int o = t / 288;
        int rem = t - o * 288;
        int c = rem / 9, tap = rem - c * 9;
        const float* src = sw + (size_t)(o * 288 + c * 9 + tap) * 8;
        float4 v0 = *(const float4*)(src);
        float4 v1 = *(const float4*)(src + 4);
        float vv[8] = {v0.x, v0.y, v0.z, v0.w, v1.x, v1.y, v1.z, v1.w};
        __half2 hh[4];
#pragma unroll
        for (int i = 0; i < 4; i++)
            hh[i] = __halves2half2(__float2half_rn(vv[2 * i]), __float2half_rn(vv[2 * i + 1]));
        *(uint4*)(g_wsh + (size_t)o * KSPL + tap * 256 + c * 8) = *(uint4*)hh;
    } else if (t < NSPL + NBAS) {
        int u = t - NSPL;
        int o = u / KBAS;
        int k = u - o * KBAS;            // k = tap*32 + c
        int tap = k >> 5, c = k & 31;
        g_wbh[u] = __float2half_rn(bw[(o * 32 + c) * 9 + tap]);
    }

    if (t >= NPIX * 32) return;
    // ---- basis fill over the PADDED grid (border gets bases(0) != 0) ----
    int c = t & 31;
    int pix = t >> 5;
    int w = pix % 58;
    int tmp = pix / 58;
    int h = tmp % 58;
    int b = tmp / 58;

    float xv = 0.0f;
    if (h >= 1 && h <= 56 && w >= 1 && w <= 56)
        xv = x[((b * 32 + c) * 56 + (h - 1)) * 56 + (w - 1)];

    float bb[8];
    bspline8(xv, bb);

    __half2 hh[4];
#pragma unroll
    for (int i = 0; i < 4; i++)
        hh[i] = __halves2half2(__float2half_rn(bb[2 * i]), __float2half_rn(bb[2 * i + 1]));
    *(uint4*)(g_fh + (size_t)pix * 256 + c * 8) = *(uint4*)hh;
    g_xph[pix * 32 + c] = __float2half_rn(xv);
}

// ---------------- kernel 2: split-K GEMM + fused last-block reduction ----------------
// grid (196, 3): 588 uniform blocks, 27 k=32 chunks each. Tile M=64 N=64,
// 128 threads (2x2 warps), 3-stage cp.async, ldmatrix fragments, fp16 single-pass.
// The last of the 3 blocks per m-tile performs the reduce+silu+scale epilogue.
#define ASTRIDE 40   // halfs per smem row (80B, conflict-free for LDS and LDSM)
#define NSTG 3

__global__ void __launch_bounds__(128) kan_mma_kernel(const float* __restrict__ scaler,
                                                      float* __restrict__ out)
{
    __shared__ __align__(16) union SmemU {
        struct { __half A[NSTG][64 * ASTRIDE]; __half B[NSTG][64 * ASTRIDE]; } p;
        float T[64][65];
    } su;
    __shared__ int sIsLast;

    const int tid  = threadIdx.x;
    const int wid  = tid >> 5, lane = tid & 31;
    const int wm   = wid >> 1, wn = wid & 1;
    const int g    = lane >> 2, tg = lane & 3;
    const int mBase = blockIdx.x * 64;
    const int z     = blockIdx.y;
    const int chBase = z * CPB;

    // loader mapping
    const int lrow = tid >> 1;
    const int lsg0 = (tid & 1) * 2;
    int lm = mBase + lrow;
    int lb = lm / 3136; int lrem = lm - lb * 3136;
    int loh = lrem / 56, low = lrem - loh * 56;
    const int ppix = (lb * 58 + loh) * 58 + low;
    const uint32_t so0 = (uint32_t)(lrow * ASTRIDE + lsg0 * 8) * 2;

    // ldmatrix lane mapping: row/col within 16x16 quad-matrix group
    const int lr8 = (lane & 7) + ((lane >> 3) & 1) * 8;   // 0..15
    const int lc8 = ((lane >> 4) & 1) * 8;                // 0 or 8

    float accS[2][4][4] = {};
    float accB[2][4][4] = {};

    auto load_stage = [&](int ch, int st) {
        const __half *ga, *gb;
        if (ch < NCH_S) {
            int tap = ch >> 3;
            int cf0 = (ch & 7) * 32;
            int toff = ((tap / 3) * 58 + (tap % 3)) * 256 + cf0;
            ga = g_fh + (size_t)ppix * 256 + toff;
            gb = g_wsh + lrow * KSPL + ch * 32;
        } else {
            int tap = ch - NCH_S;
            int toff = ((tap / 3) * 58 + (tap % 3)) * 32;
            ga = g_xph + (size_t)ppix * 32 + toff;
            gb = g_wbh + lrow * KBAS + tap * 32;
        }
        uint32_t a = smem_u32(&su.p.A[st][0]) + so0;
        uint32_t b = smem_u32(&su.p.B[st][0]) + so0;
#pragma unroll
        for (int s = 0; s < 2; s++) {
            int e = (lsg0 + s) * 8;
            CPA16(a + s * 16, ga + e);
            CPA16(b + s * 16, gb + e);
        }
    };

    auto do_chunk = [&](float (&acc)[2][4][4], int st) {
        uint32_t sa = smem_u32(&su.p.A[st][0]);
        uint32_t sb = smem_u32(&su.p.B[st][0]);
#pragma unroll
        for (int k0 = 0; k0 < 32; k0 += 16) {
            uint32_t a[2][4], bq[2][4];
#pragma unroll
            for (int mi = 0; mi < 2; mi++)
                LDSM4(a[mi], sa + (uint32_t)(((wm * 32 + mi * 16 + lr8) * ASTRIDE) + k0 + lc8) * 2);
#pragma unroll
            for (int njp = 0; njp < 2; njp++)
                LDSM4(bq[njp], sb + (uint32_t)(((wn * 32 + njp * 16 + lr8) * ASTRIDE) + k0 + lc8) * 2);
            // bq[njp] = { b[2njp][k0], b[2njp+1][k0], b[2njp][k0+8], b[2njp+1][k0+8] }
#pragma unroll
            for (int mi = 0; mi < 2; mi++)
#pragma unroll
                for (int njp = 0; njp < 2; njp++) {
                    mma16816(acc[mi][njp * 2 + 0], a[mi], bq[njp][0], bq[njp][2]);
                    mma16816(acc[mi][njp * 2 + 1], a[mi], bq[njp][1], bq[njp][3]);
                }
        }
    };

    // 3-stage pipeline, one __syncthreads per chunk
    load_stage(chBase, 0);
    CP_COMMIT();
    load_stage(chBase + 1, 1);
    CP_COMMIT();
    for (int i = 0; i < CPB; i++) {
        int ch = chBase + i;
        int st = i % NSTG;
        if (i + 2 < CPB) CP_WAIT1();
        else             CP_WAIT0();
        __syncthreads();
        if (i + 2 < CPB) {
            load_stage(ch + 2, (i + 2) % NSTG);
            CP_COMMIT();
        }
        if (ch < NCH_S) do_chunk(accS, st);
        else            do_chunk(accB, st);
    }

    // ---- store partials [m][o]; z==2 also stores base result ----
    float* Sp = g_S + (size_t)z * MTOT * 64;
#pragma unroll
    for (int mi = 0; mi < 2; mi++) {
#pragma unroll
        for (int gg = 0; gg < 2; gg++) {
            int row = wm * 32 + mi * 16 + g + gg * 8;
            size_t m = mBase + row;
#pragma unroll
            for (int nj = 0; nj < 4; nj++) {
                int o0 = wn * 32 + nj * 8 + 2 * tg;
                *(float2*)&Sp[m * 64 + o0] =
                    make_float2(accS[mi][nj][gg * 2], accS[mi][nj][gg * 2 + 1]);
                if (z == 2)
                    *(float2*)&g_Bc[m * 64 + o0] =
                        make_float2(accB[mi][nj][gg * 2], accB[mi][nj][gg * 2 + 1]);
            }
        }
    }

    // ---- last-block-done fused reduction (deterministic: sum order fixed) ----
    __threadfence();
    __syncthreads();          // also: pipeline smem no longer in use -> T reusable
    if (tid == 0) sIsLast = (atomicAdd(&g_cnt[blockIdx.x], 1) == 2);
    __syncthreads();
    if (!sIsLast) return;
    __threadfence();          // make other blocks' partials visible

    const int b = mBase / 3136, ssp0 = mBase - b * 3136;
    {   // phase 1: read [m][o] coalesced, compute, store transposed
        const int ml0 = tid >> 4;             // 0..7
        const int o4  = (tid & 15) * 4;
        float4 sc4 = *(const float4*)(scaler + o4);
        const float scv[4] = {sc4.x, sc4.y, sc4.z, sc4.w};
#pragma unroll
        for (int r = 0; r < 8; r++) {
            int ml = ml0 + r * 8;
            size_t m = mBase + ml;
            float4 s0 = *(const float4*)&g_S[m * 64 + o4];
            float4 s1 = *(const float4*)&g_S[((size_t)MTOT + m) * 64 + o4];
            float4 s2 = *(const float4*)&g_S[((size_t)2 * MTOT + m) * 64 + o4];
            float4 bv = *(const float4*)&g_Bc[m * 64 + o4];
            float ss[4] = {s0.x + s1.x + s2.x, s0.y + s1.y + s2.y,
                           s0.z + s1.z + s2.z, s0.w + s1.w + s2.w};
            float bb2[4] = {bv.x, bv.y, bv.z, bv.w};
#pragma unroll
            for (int j = 0; j < 4; j++) {
                float silu = bb2[j] / (1.0f + expf(-bb2[j]));
                su.T[o4 + j][ml] = silu + scv[j] * ss[j];
            }
        }
    }
    __syncthreads();
    {   // phase 2: write [o][m] coalesced
        const int o   = tid >> 1;             // 0..63
        const int ms0 = (tid & 1) * 32;
        float* ob = out + ((size_t)(b * 64 + o)) * 3136 + ssp0 + ms0;
#pragma unroll
        for (int j = 0; j < 8; j++) {
            int ms = ms0 + j * 4;
            *(float4*)(ob + j * 4) = make_float4(su.T[o][ms], su.T[o][ms + 1],
                                                 su.T[o][ms + 2], su.T[o][ms + 3]);
        }
    }
}

// ---------------- launch ----------------
extern "C" void kernel_launch(void* const* d_in, const int* in_sizes, int n_in,
                              void* d_out, int out_size)
{
    const float* x  = (const float*)d_in[0];  // (4,32,56,56)
    const float* bw = (const float*)d_in[1];  // (64,32,3,3)
    const float* sw = (const float*)d_in[2];  // (64,288,8)
    const float* sc = (const float*)d_in[3];  // (64,)
    float* out = (float*)d_out;               // (4,64,56,56)

    {   // 1. prep: pack weights + basis fill + zero counters
        int total = NPIX * 32;
        prep_kernel<<<(total + 255) / 256, 256>>>(x, sw, bw);
    }
    {   // 2. split-K GEMM with fused last-block reduction epilogue
        dim3 grid(MTOT / 64, 3);
        kan_mma_kernel<<<grid, 128>>>(sc, out);
    }
}